// round 10
// baseline (speedup 1.0000x reference)
#include <cuda_runtime.h>
#include <cuda_bf16.h>
#include <cstdint>

// Problem: feature_matrix (64, 1, 1000, 128) fp32 -> out (64, 1, 1000, 128, 8) fp32
#define NB        64
#define PER_B     128000                 // input elements per batch
#define TSTEPS    8
#define TPB       125                    // tiles (blocks) per batch
#define GRID_BLKS (NB * TPB)             // 8000 blocks (proven encode grid)
#define TILE_EL   1024                   // input elements per block (= 256 float4)

// ---------------------------------------------------------------------------
// Device scratch. Plain stores; per-batch ticket counters are monotone across
// graph replays (no reset needed) -> deterministic, allocation-free.
// ---------------------------------------------------------------------------
__device__ float g_part_min[GRID_BLKS];
__device__ float g_part_max[GRID_BLKS];
__device__ unsigned long long g_bar[NB];

__device__ __forceinline__ unsigned f2ord(float f) {
    unsigned u = __float_as_uint(f);
    return (u & 0x80000000u) ? ~u : (u | 0x80000000u);
}
__device__ __forceinline__ float ord2f(unsigned u) {
    u = (u & 0x80000000u) ? (u & 0x7FFFFFFFu) : ~u;
    return __uint_as_float(u);
}

struct Thresh { float t[TSTEPS]; };

// One kernel, 8000 blocks x 256. Each block: reduce its 4KB tile -> per-batch
// ticket barrier (125 arrivals) -> fold partials + bit-exact cuts -> encode
// its tile (identical proven loop: warp-contiguous full-sector STG.128, __stcs).
__global__ void __launch_bounds__(256)
fused_kernel(const float* __restrict__ in, float4* __restrict__ out, Thresh th) {
    const int tid = threadIdx.x;
    const int blk = blockIdx.x;
    const int b   = blk / TPB;           // batch 0..63

    // ---------------- Phase 1: reduce this block's 1024-element tile -------
    const float4* in4 = (const float4*)in + (size_t)blk * (TILE_EL / 4);
    float4 v = in4[tid];
    float mn = fminf(fminf(v.x, v.y), fminf(v.z, v.w));
    float mx = fmaxf(fmaxf(v.x, v.y), fmaxf(v.z, v.w));
    #pragma unroll
    for (int off = 16; off > 0; off >>= 1) {
        mn = fminf(mn, __shfl_xor_sync(0xFFFFFFFFu, mn, off));
        mx = fmaxf(mx, __shfl_xor_sync(0xFFFFFFFFu, mx, off));
    }
    __shared__ float smn[8], smx[8];
    const int wid = tid >> 5, lid = tid & 31;
    if (lid == 0) { smn[wid] = mn; smx[wid] = mx; }
    __syncthreads();

    // ---------------- Per-batch barrier (monotone ticket, replay-safe) -----
    if (tid == 0) {
        mn = smn[0]; mx = smx[0];
        #pragma unroll
        for (int w = 1; w < 8; w++) { mn = fminf(mn, smn[w]); mx = fmaxf(mx, smx[w]); }
        g_part_min[blk] = mn;
        g_part_max[blk] = mx;
        __threadfence();                                   // publish partial
        unsigned long long ticket = atomicAdd(&g_bar[b], 1ULL);
        unsigned long long target = (ticket / TPB + 1ULL) * TPB;
        while (atomicAdd(&g_bar[b], 0ULL) < target) __nanosleep(32);
        __threadfence();                                   // acquire partials
    }
    __syncthreads();

    // ---------------- Cuts (warp 0): fold 125 partials + binary search -----
    // X = max{x in [mn,mx] : RN(RN(8*RN(x-mn))/range) <= t}; monotone RN
    // stages make (norm > t) <=> (x > X) bit-identical on [mn, mx].
    __shared__ float s_cut[TSTEPS];
    if (tid < 32) {
        float bmn =  3.402823466e+38f;
        float bmx = -3.402823466e+38f;
        for (int i = tid; i < TPB; i += 32) {
            bmn = fminf(bmn, g_part_min[b * TPB + i]);
            bmx = fmaxf(bmx, g_part_max[b * TPB + i]);
        }
        #pragma unroll
        for (int off = 16; off > 0; off >>= 1) {
            bmn = fminf(bmn, __shfl_xor_sync(0xFFFFFFFFu, bmn, off));
            bmx = fmaxf(bmx, __shfl_xor_sync(0xFFFFFFFFu, bmx, off));
        }
        if (tid < TSTEPS) {
            const float range = __fsub_rn(bmx, bmn);
            const float t = th.t[tid];
            unsigned lo = f2ord(bmn), hi = f2ord(bmx);  // invariant: f(lo) <= t
            while (lo < hi) {
                unsigned mid = lo + ((hi - lo + 1u) >> 1);
                float x = ord2f(mid);
                float norm = __fdiv_rn(__fmul_rn(8.0f, __fsub_rn(x, bmn)), range);
                if (norm <= t) lo = mid; else hi = mid - 1u;
            }
            s_cut[tid] = ord2f(lo);
        }
    }
    __syncthreads();
    const int hp = (tid & 1) * 4;
    const float4 cut = make_float4(s_cut[hp], s_cut[hp + 1], s_cut[hp + 2], s_cut[hp + 3]);

    // ---------------- Phase 2: encode this tile (proven loop) --------------
    // Slot s (0..2047) = element (s>>1), time-half (s&1). Input floats for
    // this block are exactly [blk*1024, blk*1024+1024) (L2-hot from phase 1);
    // output float4 are exactly [blk*2048, blk*2048+2048).
    const float* inb  = in  + (size_t)blk * TILE_EL;
    float4*      outb = out + (size_t)blk * (TILE_EL * 2);
    #pragma unroll
    for (int k = 0; k < 8; k++) {
        const int s = k * 256 + tid;
        const float x = __ldg(inb + (s >> 1));
        float4 o;
        o.x = (x > cut.x) ? 1.0f : 0.0f;
        o.y = (x > cut.y) ? 1.0f : 0.0f;
        o.z = (x > cut.z) ? 1.0f : 0.0f;
        o.w = (x > cut.w) ? 1.0f : 0.0f;
        __stcs(outb + s, o);             // streaming: don't flush L2-hot input
    }
}

// ---------------------------------------------------------------------------
// Host: Threefry-2x32, jax.random.permutation(key(1), 8) with
// jax_threefry_partitionable=True semantics (verified rel_err=0, R2-R9):
//   split (foldlike): subkey = threefry(key, (0, 1))
//   random_bits 32-bit: bits_i = out0 ^ out1 of threefry(subkey, (0, i))
// ---------------------------------------------------------------------------
static inline uint32_t rotl32(uint32_t x, int d) { return (x << d) | (x >> (32 - d)); }

static void threefry2x32(uint32_t k0, uint32_t k1, uint32_t x0, uint32_t x1,
                         uint32_t* o0, uint32_t* o1) {
    const int rotA[4] = {13, 15, 26, 6};
    const int rotB[4] = {17, 29, 16, 24};
    uint32_t ks0 = k0, ks1 = k1, ks2 = k0 ^ k1 ^ 0x1BD11BDAu;
    x0 += ks0; x1 += ks1;
    for (int i = 0; i < 4; i++) { x0 += x1; x1 = rotl32(x1, rotA[i]); x1 ^= x0; }
    x0 += ks1; x1 += ks2 + 1u;
    for (int i = 0; i < 4; i++) { x0 += x1; x1 = rotl32(x1, rotB[i]); x1 ^= x0; }
    x0 += ks2; x1 += ks0 + 2u;
    for (int i = 0; i < 4; i++) { x0 += x1; x1 = rotl32(x1, rotA[i]); x1 ^= x0; }
    x0 += ks0; x1 += ks1 + 3u;
    for (int i = 0; i < 4; i++) { x0 += x1; x1 = rotl32(x1, rotB[i]); x1 ^= x0; }
    x0 += ks1; x1 += ks2 + 4u;
    for (int i = 0; i < 4; i++) { x0 += x1; x1 = rotl32(x1, rotA[i]); x1 ^= x0; }
    x0 += ks2; x1 += ks0 + 5u;
    *o0 = x0; *o1 = x1;
}

extern "C" void kernel_launch(void* const* d_in, const int* in_sizes, int n_in,
                              void* d_out, int out_size) {
    uint32_t sk0, sk1;
    threefry2x32(0u, 1u, 0u, 1u, &sk0, &sk1);
    uint32_t keys[8];
    for (int i = 0; i < 8; i++) {
        uint32_t o0, o1;
        threefry2x32(sk0, sk1, 0u, (uint32_t)i, &o0, &o1);
        keys[i] = o0 ^ o1;
    }
    int perm[8] = {0, 1, 2, 3, 4, 5, 6, 7};
    for (int i = 1; i < 8; i++) {           // stable insertion sort (ascending)
        uint32_t kv = keys[perm[i]];
        int p = perm[i], j = i - 1;
        while (j >= 0 && keys[perm[j]] > kv) { perm[j + 1] = perm[j]; j--; }
        perm[j + 1] = p;
    }
    Thresh th;
    for (int i = 0; i < 8; i++) th.t[i] = (float)perm[i];

    fused_kernel<<<GRID_BLKS, 256>>>((const float*)d_in[0], (float4*)d_out, th);
}

// round 12
// speedup vs baseline: 1.3859x; 1.3859x over previous
#include <cuda_runtime.h>
#include <cuda_bf16.h>
#include <cstdint>

// Problem: feature_matrix (64, 1, 1000, 128) fp32 -> out (64, 1, 1000, 128, 8) fp32
#define NB        64
#define PER_B     128000                 // elements per batch
#define PER_B4    32000                  // input float4 per batch
#define TSTEPS    8
#define RBLK      5                      // reduce blocks per batch
#define RB_F4     6400                   // float4 per reduce block = 5 iters * 5 * 256
#define EBLOCKS_PER_B 125                // encode blocks per batch (1024 elements each)

// ---------------------------------------------------------------------------
// Device scratch: per-(batch, block) partial min/max + per-batch cut values.
// Plain stores, no init kernel, no atomics, deterministic across replays.
// ---------------------------------------------------------------------------
__device__ float  g_part_min[NB * RBLK];
__device__ float  g_part_max[NB * RBLK];
__device__ float  g_cuts[NB * TSTEPS];   // [b][j]: cut for output time position j

__device__ __forceinline__ unsigned f2ord(float f) {
    unsigned u = __float_as_uint(f);
    return (u & 0x80000000u) ? ~u : (u | 0x80000000u);
}
__device__ __forceinline__ float ord2f(unsigned u) {
    u = (u & 0x80000000u) ? (u & 0x7FFFFFFFu) : ~u;
    return __uint_as_float(u);
}

struct Thresh { float t[TSTEPS]; };

// grid: (RBLK, NB), block: 256. Each block: 6400 float4 (100KB) in 5 loop
// iterations of 5 front-batched independent LDG.128 per thread. (Proven R7.)
__global__ void __launch_bounds__(256) minmax_kernel(const float4* __restrict__ in) {
    const int b = blockIdx.y;
    const float4* base = in + (size_t)b * PER_B4 + (size_t)blockIdx.x * RB_F4
                            + threadIdx.x;

    float mn =  3.402823466e+38f;
    float mx = -3.402823466e+38f;
    #pragma unroll
    for (int it = 0; it < 5; it++) {
        float4 v0 = base[it * 1280 +    0];
        float4 v1 = base[it * 1280 +  256];
        float4 v2 = base[it * 1280 +  512];
        float4 v3 = base[it * 1280 +  768];
        float4 v4 = base[it * 1280 + 1024];

        float a0 = fminf(fminf(v0.x, v0.y), fminf(v0.z, v0.w));
        float b0 = fmaxf(fmaxf(v0.x, v0.y), fmaxf(v0.z, v0.w));
        float a1 = fminf(fminf(v1.x, v1.y), fminf(v1.z, v1.w));
        float b1 = fmaxf(fmaxf(v1.x, v1.y), fmaxf(v1.z, v1.w));
        float a2 = fminf(fminf(v2.x, v2.y), fminf(v2.z, v2.w));
        float b2 = fmaxf(fmaxf(v2.x, v2.y), fmaxf(v2.z, v2.w));
        float a3 = fminf(fminf(v3.x, v3.y), fminf(v3.z, v3.w));
        float b3 = fmaxf(fmaxf(v3.x, v3.y), fmaxf(v3.z, v3.w));
        float a4 = fminf(fminf(v4.x, v4.y), fminf(v4.z, v4.w));
        float b4 = fmaxf(fmaxf(v4.x, v4.y), fmaxf(v4.z, v4.w));

        mn = fminf(mn, fminf(fminf(fminf(a0, a1), fminf(a2, a3)), a4));
        mx = fmaxf(mx, fmaxf(fmaxf(fmaxf(b0, b1), fmaxf(b2, b3)), b4));
    }

    #pragma unroll
    for (int off = 16; off > 0; off >>= 1) {
        mn = fminf(mn, __shfl_xor_sync(0xFFFFFFFFu, mn, off));
        mx = fmaxf(mx, __shfl_xor_sync(0xFFFFFFFFu, mx, off));
    }
    __shared__ float smn[8], smx[8];
    const int wid = threadIdx.x >> 5, lid = threadIdx.x & 31;
    if (lid == 0) { smn[wid] = mn; smx[wid] = mx; }
    __syncthreads();
    if (threadIdx.x == 0) {
        mn = smn[0]; mx = smx[0];
        #pragma unroll
        for (int w = 1; w < 8; w++) { mn = fminf(mn, smn[w]); mx = fmaxf(mx, smx[w]); }
        g_part_min[b * RBLK + blockIdx.x] = mn;
        g_part_max[b * RBLK + blockIdx.x] = mx;
    }
}

// 1 block, 512 threads = 64 batches x 8 output positions.
// X = max{x in [mn,mx] : RN(RN(8*RN(x-mn))/range) <= t}, binary search over
// ordered-float bits with the reference's exact IEEE-RN formula; monotone RN
// stages make (norm > t) <=> (x > X) bit-identical on [mn, mx].
__global__ void __launch_bounds__(512) cuts_kernel(Thresh th) {
    const int b = threadIdx.x >> 3;      // 0..63
    const int j = threadIdx.x & 7;       // output time position 0..7

    float mn =  3.402823466e+38f;
    float mx = -3.402823466e+38f;
    #pragma unroll
    for (int i = 0; i < RBLK; i++) {
        mn = fminf(mn, g_part_min[b * RBLK + i]);
        mx = fmaxf(mx, g_part_max[b * RBLK + i]);
    }
    const float range = __fsub_rn(mx, mn);
    const float t = th.t[j];

    unsigned lo = f2ord(mn), hi = f2ord(mx);   // invariant: f(lo) <= t (f(mn)=0)
    while (lo < hi) {
        unsigned mid = lo + ((hi - lo + 1u) >> 1);
        float x = ord2f(mid);
        float norm = __fdiv_rn(__fmul_rn(8.0f, __fsub_rn(x, mn)), range);
        if (norm <= t) lo = mid; else hi = mid - 1u;
    }
    g_cuts[b * 8 + j] = ord2f(lo);
}

// One thread per input element per iteration: 1 LDG.32 (perfectly coalesced,
// each float read exactly once) + 8 compares + 1 STG.256 (32B row, 32B
// aligned; warp = 1024B contiguous). 4 iterations/thread.
// grid: 8000 blocks x 256 threads; block covers 1024 elements.
__global__ void __launch_bounds__(256) encode_kernel(const float* __restrict__ in,
                                                     float* __restrict__ out) {
    const int tid = threadIdx.x;
    const int b   = blockIdx.x / EBLOCKS_PER_B;

    const float c0 = g_cuts[b * 8 + 0], c1 = g_cuts[b * 8 + 1];
    const float c2 = g_cuts[b * 8 + 2], c3 = g_cuts[b * 8 + 3];
    const float c4 = g_cuts[b * 8 + 4], c5 = g_cuts[b * 8 + 5];
    const float c6 = g_cuts[b * 8 + 6], c7 = g_cuts[b * 8 + 7];

    const int ebase = blockIdx.x * 1024 + tid;
    #pragma unroll
    for (int k = 0; k < 4; k++) {
        const int e = ebase + k * 256;
        const float x = __ldg(in + e);
        const float o0 = (x > c0) ? 1.0f : 0.0f;
        const float o1 = (x > c1) ? 1.0f : 0.0f;
        const float o2 = (x > c2) ? 1.0f : 0.0f;
        const float o3 = (x > c3) ? 1.0f : 0.0f;
        const float o4 = (x > c4) ? 1.0f : 0.0f;
        const float o5 = (x > c5) ? 1.0f : 0.0f;
        const float o6 = (x > c6) ? 1.0f : 0.0f;
        const float o7 = (x > c7) ? 1.0f : 0.0f;
        // 256-bit streaming store (sm_100+): one element's full output row.
        asm volatile(
            "st.global.cs.v8.f32 [%0], {%1, %2, %3, %4, %5, %6, %7, %8};"
            :: "l"(out + (size_t)e * 8),
               "f"(o0), "f"(o1), "f"(o2), "f"(o3),
               "f"(o4), "f"(o5), "f"(o6), "f"(o7)
            : "memory");
    }
}

// ---------------------------------------------------------------------------
// Host: Threefry-2x32, jax.random.permutation(key(1), 8) with
// jax_threefry_partitionable=True semantics (verified rel_err=0, R2-R10):
//   split (foldlike): subkey = threefry(key, (0, 1))
//   random_bits 32-bit: bits_i = out0 ^ out1 of threefry(subkey, (0, i))
// ---------------------------------------------------------------------------
static inline uint32_t rotl32(uint32_t x, int d) { return (x << d) | (x >> (32 - d)); }

static void threefry2x32(uint32_t k0, uint32_t k1, uint32_t x0, uint32_t x1,
                         uint32_t* o0, uint32_t* o1) {
    const int rotA[4] = {13, 15, 26, 6};
    const int rotB[4] = {17, 29, 16, 24};
    uint32_t ks0 = k0, ks1 = k1, ks2 = k0 ^ k1 ^ 0x1BD11BDAu;
    x0 += ks0; x1 += ks1;
    for (int i = 0; i < 4; i++) { x0 += x1; x1 = rotl32(x1, rotA[i]); x1 ^= x0; }
    x0 += ks1; x1 += ks2 + 1u;
    for (int i = 0; i < 4; i++) { x0 += x1; x1 = rotl32(x1, rotB[i]); x1 ^= x0; }
    x0 += ks2; x1 += ks0 + 2u;
    for (int i = 0; i < 4; i++) { x0 += x1; x1 = rotl32(x1, rotA[i]); x1 ^= x0; }
    x0 += ks0; x1 += ks1 + 3u;
    for (int i = 0; i < 4; i++) { x0 += x1; x1 = rotl32(x1, rotB[i]); x1 ^= x0; }
    x0 += ks1; x1 += ks2 + 4u;
    for (int i = 0; i < 4; i++) { x0 += x1; x1 = rotl32(x1, rotA[i]); x1 ^= x0; }
    x0 += ks2; x1 += ks0 + 5u;
    *o0 = x0; *o1 = x1;
}

extern "C" void kernel_launch(void* const* d_in, const int* in_sizes, int n_in,
                              void* d_out, int out_size) {
    uint32_t sk0, sk1;
    threefry2x32(0u, 1u, 0u, 1u, &sk0, &sk1);
    uint32_t keys[8];
    for (int i = 0; i < 8; i++) {
        uint32_t o0, o1;
        threefry2x32(sk0, sk1, 0u, (uint32_t)i, &o0, &o1);
        keys[i] = o0 ^ o1;
    }
    int perm[8] = {0, 1, 2, 3, 4, 5, 6, 7};
    for (int i = 1; i < 8; i++) {           // stable insertion sort (ascending)
        uint32_t kv = keys[perm[i]];
        int p = perm[i], j = i - 1;
        while (j >= 0 && keys[perm[j]] > kv) { perm[j + 1] = perm[j]; j--; }
        perm[j + 1] = p;
    }
    Thresh th;
    for (int i = 0; i < 8; i++) th.t[i] = (float)perm[i];

    const float* in_f = (const float*)d_in[0];

    dim3 rgrid(RBLK, NB);
    minmax_kernel<<<rgrid, 256>>>((const float4*)in_f);
    cuts_kernel<<<1, 512>>>(th);
    encode_kernel<<<NB * EBLOCKS_PER_B, 256>>>(in_f, (float*)d_out);
}

// round 13
// speedup vs baseline: 1.5337x; 1.1066x over previous
#include <cuda_runtime.h>
#include <cuda_bf16.h>
#include <cstdint>

// Problem: feature_matrix (64, 1, 1000, 128) fp32 -> out (64, 1, 1000, 128, 8) fp32
#define NB        64
#define PER_B     128000                 // elements per batch
#define PER_B4    32000                  // input float4 per batch
#define TSTEPS    8
#define RBLK      5                      // reduce blocks per batch
#define RB_F4     6400                   // float4 per reduce block = 5 iters * 5 * 256
#define EBLOCKS_PER_B 125                // encode blocks per batch (2048 out-float4 each)

// ---------------------------------------------------------------------------
// Device scratch: per-(batch, block) partial min/max + per-batch cut values.
// Plain stores, no init kernel, no atomics, deterministic across replays.
// ---------------------------------------------------------------------------
__device__ float  g_part_min[NB * RBLK];
__device__ float  g_part_max[NB * RBLK];
__device__ float4 g_cuts4[NB * 2];       // [b][parity]: cuts for out positions 0-3 / 4-7

__device__ __forceinline__ unsigned f2ord(float f) {
    unsigned u = __float_as_uint(f);
    return (u & 0x80000000u) ? ~u : (u | 0x80000000u);
}
__device__ __forceinline__ float ord2f(unsigned u) {
    u = (u & 0x80000000u) ? (u & 0x7FFFFFFFu) : ~u;
    return __uint_as_float(u);
}

// grid: (RBLK, NB), block: 256. Each block: 6400 float4 (100KB) in 5 loop
// iterations of 5 front-batched independent LDG.128 per thread.
__global__ void __launch_bounds__(256) minmax_kernel(const float4* __restrict__ in) {
    const int b = blockIdx.y;
    const float4* base = in + (size_t)b * PER_B4 + (size_t)blockIdx.x * RB_F4
                            + threadIdx.x;

    float mn =  3.402823466e+38f;
    float mx = -3.402823466e+38f;
    #pragma unroll
    for (int it = 0; it < 5; it++) {
        // 5 independent loads, front-batched (no dependent ops between them)
        float4 v0 = base[it * 1280 +    0];
        float4 v1 = base[it * 1280 +  256];
        float4 v2 = base[it * 1280 +  512];
        float4 v3 = base[it * 1280 +  768];
        float4 v4 = base[it * 1280 + 1024];

        float a0 = fminf(fminf(v0.x, v0.y), fminf(v0.z, v0.w));
        float b0 = fmaxf(fmaxf(v0.x, v0.y), fmaxf(v0.z, v0.w));
        float a1 = fminf(fminf(v1.x, v1.y), fminf(v1.z, v1.w));
        float b1 = fmaxf(fmaxf(v1.x, v1.y), fmaxf(v1.z, v1.w));
        float a2 = fminf(fminf(v2.x, v2.y), fminf(v2.z, v2.w));
        float b2 = fmaxf(fmaxf(v2.x, v2.y), fmaxf(v2.z, v2.w));
        float a3 = fminf(fminf(v3.x, v3.y), fminf(v3.z, v3.w));
        float b3 = fmaxf(fmaxf(v3.x, v3.y), fmaxf(v3.z, v3.w));
        float a4 = fminf(fminf(v4.x, v4.y), fminf(v4.z, v4.w));
        float b4 = fmaxf(fmaxf(v4.x, v4.y), fmaxf(v4.z, v4.w));

        mn = fminf(mn, fminf(fminf(fminf(a0, a1), fminf(a2, a3)), a4));
        mx = fmaxf(mx, fmaxf(fmaxf(fmaxf(b0, b1), fmaxf(b2, b3)), b4));
    }

    #pragma unroll
    for (int off = 16; off > 0; off >>= 1) {
        mn = fminf(mn, __shfl_xor_sync(0xFFFFFFFFu, mn, off));
        mx = fmaxf(mx, __shfl_xor_sync(0xFFFFFFFFu, mx, off));
    }
    __shared__ float smn[8], smx[8];
    const int wid = threadIdx.x >> 5, lid = threadIdx.x & 31;
    if (lid == 0) { smn[wid] = mn; smx[wid] = mx; }
    __syncthreads();
    if (threadIdx.x == 0) {
        mn = smn[0]; mx = smx[0];
        #pragma unroll
        for (int w = 1; w < 8; w++) { mn = fminf(mn, smn[w]); mx = fmaxf(mx, smx[w]); }
        g_part_min[b * RBLK + blockIdx.x] = mn;
        g_part_max[b * RBLK + blockIdx.x] = mx;
    }
}

struct Thresh { float t[TSTEPS]; };

// 1 block, 512 threads = 64 batches x 8 output positions.
// X = max{x in [mn,mx] : RN(RN(8*RN(x-mn))/range) <= t}, binary search over
// ordered-float bits with the reference's exact IEEE-RN formula; monotone RN
// stages make (norm > t) <=> (x > X) bit-identical on [mn, mx].
__global__ void __launch_bounds__(512) cuts_kernel(Thresh th) {
    const int b = threadIdx.x >> 3;      // 0..63
    const int j = threadIdx.x & 7;       // output time position 0..7

    float mn =  3.402823466e+38f;
    float mx = -3.402823466e+38f;
    #pragma unroll
    for (int i = 0; i < RBLK; i++) {
        mn = fminf(mn, g_part_min[b * RBLK + i]);
        mx = fmaxf(mx, g_part_max[b * RBLK + i]);
    }
    const float range = __fsub_rn(mx, mn);
    const float t = th.t[j];

    unsigned lo = f2ord(mn), hi = f2ord(mx);   // invariant: f(lo) <= t (f(mn)=0)
    while (lo < hi) {
        unsigned mid = lo + ((hi - lo + 1u) >> 1);
        float x = ord2f(mid);
        float norm = __fdiv_rn(__fmul_rn(8.0f, __fsub_rn(x, mn)), range);
        if (norm <= t) lo = mid; else hi = mid - 1u;
    }
    reinterpret_cast<float*>(g_cuts4)[b * 8 + j] = ord2f(lo);
}

// One thread -> 8 output float4 slots (warp-contiguous 512B stores, full
// sectors). Slot s = element (s>>1), time-half (s&1). Streaming stores keep
// the 32MB input L2-resident (loaded by minmax) so encode reads hit L2.
// grid: 8000 blocks x 256 threads; block covers 2048 slots = 1024 elements.
__global__ void __launch_bounds__(256) encode_kernel(const float* __restrict__ in,
                                                     float4* __restrict__ out) {
    const int tid = threadIdx.x;
    const int b   = blockIdx.x / EBLOCKS_PER_B;
    const float4 cut = g_cuts4[b * 2 + (tid & 1)];

    const int base_s = blockIdx.x * 2048 + tid;
    #pragma unroll
    for (int k = 0; k < 8; k++) {
        const int s = base_s + k * 256;
        const float x = __ldg(in + (s >> 1));
        float4 o;
        o.x = (x > cut.x) ? 1.0f : 0.0f;
        o.y = (x > cut.y) ? 1.0f : 0.0f;
        o.z = (x > cut.z) ? 1.0f : 0.0f;
        o.w = (x > cut.w) ? 1.0f : 0.0f;
        __stcs(out + s, o);              // evict-first: don't flush input from L2
    }
}

// ---------------------------------------------------------------------------
// Host: Threefry-2x32, jax.random.permutation(key(1), 8) with
// jax_threefry_partitionable=True semantics (verified rel_err=0, R2-R12):
//   split (foldlike): subkey = threefry(key, (0, 1))
//   random_bits 32-bit: bits_i = out0 ^ out1 of threefry(subkey, (0, i))
// ---------------------------------------------------------------------------
static inline uint32_t rotl32(uint32_t x, int d) { return (x << d) | (x >> (32 - d)); }

static void threefry2x32(uint32_t k0, uint32_t k1, uint32_t x0, uint32_t x1,
                         uint32_t* o0, uint32_t* o1) {
    const int rotA[4] = {13, 15, 26, 6};
    const int rotB[4] = {17, 29, 16, 24};
    uint32_t ks0 = k0, ks1 = k1, ks2 = k0 ^ k1 ^ 0x1BD11BDAu;
    x0 += ks0; x1 += ks1;
    for (int i = 0; i < 4; i++) { x0 += x1; x1 = rotl32(x1, rotA[i]); x1 ^= x0; }
    x0 += ks1; x1 += ks2 + 1u;
    for (int i = 0; i < 4; i++) { x0 += x1; x1 = rotl32(x1, rotB[i]); x1 ^= x0; }
    x0 += ks2; x1 += ks0 + 2u;
    for (int i = 0; i < 4; i++) { x0 += x1; x1 = rotl32(x1, rotA[i]); x1 ^= x0; }
    x0 += ks0; x1 += ks1 + 3u;
    for (int i = 0; i < 4; i++) { x0 += x1; x1 = rotl32(x1, rotB[i]); x1 ^= x0; }
    x0 += ks1; x1 += ks2 + 4u;
    for (int i = 0; i < 4; i++) { x0 += x1; x1 = rotl32(x1, rotA[i]); x1 ^= x0; }
    x0 += ks2; x1 += ks0 + 5u;
    *o0 = x0; *o1 = x1;
}

extern "C" void kernel_launch(void* const* d_in, const int* in_sizes, int n_in,
                              void* d_out, int out_size) {
    uint32_t sk0, sk1;
    threefry2x32(0u, 1u, 0u, 1u, &sk0, &sk1);
    uint32_t keys[8];
    for (int i = 0; i < 8; i++) {
        uint32_t o0, o1;
        threefry2x32(sk0, sk1, 0u, (uint32_t)i, &o0, &o1);
        keys[i] = o0 ^ o1;
    }
    int perm[8] = {0, 1, 2, 3, 4, 5, 6, 7};
    for (int i = 1; i < 8; i++) {           // stable insertion sort (ascending)
        uint32_t kv = keys[perm[i]];
        int p = perm[i], j = i - 1;
        while (j >= 0 && keys[perm[j]] > kv) { perm[j + 1] = perm[j]; j--; }
        perm[j + 1] = p;
    }
    Thresh th;
    for (int i = 0; i < 8; i++) th.t[i] = (float)perm[i];

    const float* in_f = (const float*)d_in[0];

    dim3 rgrid(RBLK, NB);
    minmax_kernel<<<rgrid, 256>>>((const float4*)in_f);
    cuts_kernel<<<1, 512>>>(th);
    encode_kernel<<<NB * EBLOCKS_PER_B, 256>>>(in_f, (float4*)d_out);
}